// round 8
// baseline (speedup 1.0000x reference)
#include <cuda_runtime.h>
#include <cstdint>

// ScaledDotProductAttention: B=4, W=64, H=64, C=256, M=32, D=32, T=8
// out[b,c,w,h] = sum_m v[b,w,h,c,m] * softmax_m( (q[b,w,h,m,:] . k[b,w,h,:]) / T )
//
// Pure HBM-streaming kernel (594 MB moved once).
// R3 (best so far, 90.6us / DRAM 85.8%): coalesced 512B warp loads + shfls.
// R4-R7: every register-funded MLP experiment regressed -> RF is the MLP cap.
// R8: v streamed via cp.async.bulk (UBLKCP) into double-buffered smem tiles
//     behind mbarriers. MLP now lives in the async engine (2 x 32KB in flight
//     per CTA), not registers. Compute reads smem conflict-free (512B/warp).

#define C_DIM 256
#define M_DIM 32
#define D_DIM 32
#define W_DIM 64
#define H_DIM 64
#define HT 16

#define VTILE_BYTES (C_DIM * M_DIM * 4)          // 32768 bytes per h-slice
#define OFF_VBUF 0
#define OFF_MBAR (2 * VTILE_BYTES)               // 65536
#define OFF_WTS  (OFF_MBAR + 16)                 // 65552 (16B aligned)
#define OFF_RES  (OFF_WTS + HT * M_DIM * 4)      // 67600 (16B aligned)
#define SMEM_TOTAL (OFF_RES + C_DIM * (HT + 1) * 4)  // 85008

#define MBAR_WAIT(mb, ph) do {                                                   \
    uint32_t _done;                                                              \
    asm volatile("{\n\t.reg .pred p;\n\t"                                        \
        "mbarrier.try_wait.parity.acquire.cta.shared::cta.b64 p, [%1], %2;\n\t"  \
        "selp.b32 %0, 1, 0, p;\n\t}"                                             \
        : "=r"(_done) : "r"(mb), "r"(ph) : "memory");                            \
    while (!_done) {                                                             \
        asm volatile("{\n\t.reg .pred p;\n\t"                                    \
            "mbarrier.try_wait.parity.acquire.cta.shared::cta.b64 p, [%1], %2, 0x989680;\n\t" \
            "selp.b32 %0, 1, 0, p;\n\t}"                                         \
            : "=r"(_done) : "r"(mb), "r"(ph) : "memory");                        \
    }                                                                            \
} while (0)

__global__ __launch_bounds__(128, 2)
void sdpa_kernel(const float* __restrict__ q,
                 const float* __restrict__ v,
                 const float* __restrict__ k,
                 float* __restrict__ out)
{
    extern __shared__ char smem[];
    float* wts = (float*)(smem + OFF_WTS);       // [h_local][m] softmax weights
    float* res = (float*)(smem + OFF_RES);       // [c][h_local], +1 pad

    uint32_t smem_base;
    asm("{ .reg .u64 t; cvta.to.shared.u64 t, %1; cvt.u32.u64 %0, t; }"
        : "=r"(smem_base) : "l"(smem));
    const uint32_t mbar0 = smem_base + OFF_MBAR;

    const int hq = blockIdx.x;               // 0..3
    const int w  = blockIdx.y;               // 0..63
    const int b  = blockIdx.z;               // 0..3
    const int h0 = hq * HT;

    const int tid  = threadIdx.x;
    const int lane = tid & 31;
    const int wid  = tid >> 5;               // 0..3
    const int sub  = lane & 7;
    const int grp  = lane >> 3;

    const long slice0 = ((long)(b * W_DIM + w) * H_DIM + h0);
    const float* __restrict__ vslice = v + slice0 * (long)(C_DIM * M_DIM);

    // ---------- init mbarriers, then kick off the first two bulk copies ----------
    if (tid == 0) {
        asm volatile("mbarrier.init.shared.b64 [%0], 1;" :: "r"(mbar0)     : "memory");
        asm volatile("mbarrier.init.shared.b64 [%0], 1;" :: "r"(mbar0 + 8) : "memory");
    }
    __syncthreads();
    if (tid == 0) {
        #pragma unroll
        for (int s = 0; s < 2; ++s) {
            const uint32_t mb  = mbar0 + 8 * s;
            const uint32_t dst = smem_base + OFF_VBUF + s * VTILE_BYTES;
            const uint32_t nbytes = VTILE_BYTES;
            asm volatile("mbarrier.arrive.expect_tx.shared.b64 _, [%0], %1;"
                         :: "r"(mb), "r"(nbytes) : "memory");
            asm volatile("cp.async.bulk.shared::cta.global.mbarrier::complete_tx::bytes "
                         "[%0], [%1], %2, [%3];"
                         :: "r"(dst), "l"(vslice + (long)s * (C_DIM * M_DIM)),
                            "r"(nbytes), "r"(mb) : "memory");
        }
    }

    // ---------- Phase 1: softmax weights (overlaps with the in-flight copies) ----------
    #pragma unroll
    for (int i = 0; i < 4; ++i) {
        const int  hl = wid * 4 + i;
        const long sl = slice0 + hl;

        const float4 k4 = *(const float4*)(k + sl * D_DIM + sub * 4);

        #pragma unroll
        for (int j = 0; j < 8; ++j) {
            const int m = j * 4 + grp;
            const float4 q4 = *(const float4*)(q + (sl * M_DIM + m) * D_DIM + sub * 4);
            float p = q4.x * k4.x + q4.y * k4.y + q4.z * k4.z + q4.w * k4.w;
            p += __shfl_xor_sync(0xffffffffu, p, 4);
            p += __shfl_xor_sync(0xffffffffu, p, 2);
            p += __shfl_xor_sync(0xffffffffu, p, 1);
            if (sub == 0) wts[hl * M_DIM + m] = p;   // raw logit
        }
        __syncwarp();

        const float logit = wts[hl * M_DIM + lane] * 0.125f;  // 1/TEMPERATURE
        float mx = logit;
        #pragma unroll
        for (int o = 16; o; o >>= 1) mx = fmaxf(mx, __shfl_xor_sync(0xffffffffu, mx, o));
        const float e = __expf(logit - mx);
        float s = e;
        #pragma unroll
        for (int o = 16; o; o >>= 1) s += __shfl_xor_sync(0xffffffffu, s, o);
        wts[hl * M_DIM + lane] = e / s;
    }
    __syncthreads();

    // ---------- Phase 2: consume smem tiles; warp owns 64 c-values ----------
    const int cbase = wid * 64;
    for (int hl = 0; hl < HT; ++hl) {
        const int st      = hl & 1;
        const uint32_t mb = mbar0 + 8 * st;
        const uint32_t ph = (hl >> 1) & 1;

        MBAR_WAIT(mb, ph);   // tile ready (acquire orders subsequent smem reads)

        const float* __restrict__ vb = (const float*)(smem + OFF_VBUF + st * VTILE_BYTES);
        const float4 w4 = *(const float4*)(wts + hl * M_DIM + sub * 4);
        #pragma unroll
        for (int j = 0; j < 16; ++j) {
            const int c = cbase + j * 4 + grp;
            const float4 v4 = *(const float4*)(vb + c * M_DIM + sub * 4);  // 512B/warp, conflict-free
            float p = v4.x * w4.x + v4.y * w4.y + v4.z * w4.z + v4.w * w4.w;
            p += __shfl_xor_sync(0xffffffffu, p, 4);
            p += __shfl_xor_sync(0xffffffffu, p, 2);
            p += __shfl_xor_sync(0xffffffffu, p, 1);
            if (sub == 0) res[c * (HT + 1) + hl] = p;
        }
        __syncthreads();     // everyone done with buffer st before refill

        if (tid == 0 && hl + 2 < HT) {
            const uint32_t dst = smem_base + OFF_VBUF + st * VTILE_BYTES;
            const uint32_t nbytes = VTILE_BYTES;
            asm volatile("mbarrier.arrive.expect_tx.shared.b64 _, [%0], %1;"
                         :: "r"(mb), "r"(nbytes) : "memory");
            asm volatile("cp.async.bulk.shared::cta.global.mbarrier::complete_tx::bytes "
                         "[%0], [%1], %2, [%3];"
                         :: "r"(dst), "l"(vslice + (long)(hl + 2) * (C_DIM * M_DIM)),
                            "r"(nbytes), "r"(mb) : "memory");
        }
    }

    // ---------- Phase 3: coalesced transposed writes: out[((b*C + c)*W + w)*H + h] ----------
    #pragma unroll
    for (int it = 0; it < 8; ++it) {
        const int j  = it * 128 + tid;
        const int c2 = j >> 2;            // 0..255
        const int hb = (j & 3) << 2;      // 0,4,8,12
        const float* r = &res[c2 * (HT + 1) + hb];
        const float4 o4 = make_float4(r[0], r[1], r[2], r[3]);
        const long oidx = (((long)b * C_DIM + c2) * W_DIM + w) * H_DIM + (h0 + hb);
        __stcs((float4*)(out + oidx), o4);
    }
}

extern "C" void kernel_launch(void* const* d_in, const int* in_sizes, int n_in,
                              void* d_out, int out_size)
{
    // Resolve inputs by element count: q=16,777,216; v=134,217,728; k=524,288
    const float* q = nullptr;
    const float* v = nullptr;
    const float* k = nullptr;
    for (int i = 0; i < n_in; ++i) {
        if (in_sizes[i] == 16777216)       q = (const float*)d_in[i];
        else if (in_sizes[i] == 134217728) v = (const float*)d_in[i];
        else if (in_sizes[i] == 524288)    k = (const float*)d_in[i];
    }
    float* out = (float*)d_out;

    cudaFuncSetAttribute(sdpa_kernel, cudaFuncAttributeMaxDynamicSharedMemorySize, SMEM_TOTAL);

    dim3 grid(H_DIM / HT, W_DIM, 4);   // (4, 64, 4) = 1024 CTAs
    sdpa_kernel<<<grid, 128, SMEM_TOTAL>>>(q, v, k, out);
}